// round 2
// baseline (speedup 1.0000x reference)
#include <cuda_runtime.h>
#include <cuda_bf16.h>
#include <cstdint>

// ============================================================================
// QuantizedLinear (sm_103 base-PTX build — tcgen05 unavailable in this
// toolchain config, so we use classic mma.sync s8 IMMA).
//
//   y[m][n] = (sum_k x[m][k] * wq[n][k]) * scale + bias[n]
//   M=16384, N=4096, K=4096, fp32 out.
//
// Math: x -> fixed point v = rint(x*2048), split v = 128*h + l (h,l int8).
//       wq -> int8 exact. Two s8 GEMMs (h*w, l*w) sharing B fragments.
//       y = (128*acc_h + acc_l) * (scale/2048) + bias.   rel err ~7e-5.
//
// pack_a/pack_b pre-arrange data in exact mma.sync fragment order so the
// GEMM main loop does only linear LDS.128/LDS.64 (no ldmatrix, no conflicts).
// Pipeline: 6-stage cp.async.bulk + mbarrier.
// ============================================================================

#define M_TOTAL 16384
#define N_TOTAL 4096
#define K_TOTAL 4096
#define NUM_KS  64            // K chunks of 64
#define NUM_MT  128           // M tiles of 128
#define NUM_NT  32            // N tiles of 128
#define STAGES  6

#define A_CHUNK_BYTES 16384   // 128m x 64k x 2 planes (h,l) int8, frag-ordered
#define B_CHUNK_BYTES 8192    // 128n x 64k int8, frag-ordered
#define STAGE_BYTES   (A_CHUNK_BYTES + B_CHUNK_BYTES)   // 24576

#define SMEM_BIAS   512
#define SMEM_STAGE0 1024
#define DYN_SMEM    (SMEM_STAGE0 + STAGES * STAGE_BYTES)  // 148480

// scratch: frag-ordered planes
__device__ __align__(1024) unsigned char g_A[(size_t)NUM_MT * NUM_KS * A_CHUNK_BYTES]; // 128 MB
__device__ __align__(1024) unsigned char g_B[(size_t)NUM_NT * NUM_KS * B_CHUNK_BYTES]; //  16 MB

// ---------------------------------------------------------------------------
// helpers
// ---------------------------------------------------------------------------
__device__ __forceinline__ uint32_t smem_u32(const void* p) {
    uint32_t a;
    asm("{ .reg .u64 t; cvta.to.shared.u64 t, %1; cvt.u32.u64 %0, t; }" : "=r"(a) : "l"(p));
    return a;
}

#define MBARRIER_INIT(addr, cnt) \
    asm volatile("mbarrier.init.shared.b64 [%0], %1;" :: "r"((uint32_t)(addr)), "r"((uint32_t)(cnt)) : "memory")
#define MBARRIER_EXPECT_TX(addr, bytes) \
    asm volatile("mbarrier.arrive.expect_tx.shared.b64 _, [%0], %1;" :: "r"((uint32_t)(addr)), "r"((uint32_t)(bytes)) : "memory")

#define MBARRIER_WAIT_PARITY(addr, parity) do {                                   \
    uint32_t _m = (uint32_t)(addr); uint32_t _p = (uint32_t)(parity); uint32_t _d;\
    asm volatile("{\n\t.reg .pred p;\n\t"                                         \
        "mbarrier.try_wait.parity.acquire.cta.shared::cta.b64 p, [%1], %2;\n\t"   \
        "selp.b32 %0, 1, 0, p;\n\t}"                                              \
        : "=r"(_d) : "r"(_m), "r"(_p) : "memory");                                \
    if (!_d) {                                                                    \
        asm volatile("{\n\t.reg .pred P1;\n\t"                                    \
            "WAIT_LOOP_%=:\n\t"                                                   \
            "mbarrier.try_wait.parity.acquire.cta.shared::cta.b64 P1, [%0], %1, 0x989680;\n\t" \
            "@P1 bra.uni WAIT_DONE_%=;\n\t"                                       \
            "bra.uni WAIT_LOOP_%=;\n\t"                                           \
            "WAIT_DONE_%=:\n\t}"                                                  \
            :: "r"(_m), "r"(_p) : "memory");                                      \
    }                                                                             \
} while (0)

__device__ __forceinline__ void bulk_g2s(uint32_t dst, const void* src,
                                         uint32_t bytes, uint32_t mbar) {
    asm volatile(
        "cp.async.bulk.shared::cluster.global.mbarrier::complete_tx::bytes [%0], [%1], %2, [%3];"
        :: "r"(dst), "l"(src), "r"(bytes), "r"(mbar) : "memory");
}

// s8 IMMA: D(s32, m16n8) += A(s8, m16k32) * B(s8, k32n8)
__device__ __forceinline__ void mma_s8(int* d, const uint32_t* a, const uint32_t* b) {
    asm volatile(
        "mma.sync.aligned.m16n8k32.row.col.s32.s8.s8.s32 "
        "{%0,%1,%2,%3}, {%4,%5,%6,%7}, {%8,%9}, {%0,%1,%2,%3};"
        : "+r"(d[0]), "+r"(d[1]), "+r"(d[2]), "+r"(d[3])
        : "r"(a[0]), "r"(a[1]), "r"(a[2]), "r"(a[3]), "r"(b[0]), "r"(b[1]));
}

// ---------------------------------------------------------------------------
// pack_a: x fp32 -> (h,l) s8 planes in mma fragment order.
// A chunk (mtile, ks): 512 frag-slots x 16B per plane; slot
//   fl = ((mw*2+kk)*2+mt)*32 + lane ; bytes: [r0,k0..3][r0+8,k0..3][r0,k16..19][r0+8,k16..19]
//   with r0 = lane>>2, k0 = kchunk + kk*32 + (lane&3)*4.
// One thread produces one 16B h-frag + one 16B l-frag.
// ---------------------------------------------------------------------------
__device__ __forceinline__ void cvt4(float4 v, uint32_t& hw, uint32_t& lw) {
    float f[4] = {v.x, v.y, v.z, v.w};
    uint32_t h = 0, l = 0;
#pragma unroll
    for (int i = 0; i < 4; i++) {
        int q = __float2int_rn(f[i] * 2048.0f);
        q = max(-16256, min(16256, q));
        int hi = (q + 64) >> 7;          // [-127,127]
        int lo = q - (hi << 7);          // [-64,63]
        h |= (uint32_t)(hi & 0xFF) << (8 * i);
        l |= (uint32_t)(lo & 0xFF) << (8 * i);
    }
    hw = h; lw = l;
}

__global__ void __launch_bounds__(256) pack_a_kernel(const float* __restrict__ x) {
    const int t = blockIdx.x * 256 + threadIdx.x;     // 4,194,304 threads
    const int mtile = t >> 15;
    const int rem   = t & 32767;
    const int ks    = rem >> 9;
    const int fl    = rem & 511;
    const int mw = fl >> 7, kk = (fl >> 6) & 1, mt = (fl >> 5) & 1, lane = fl & 31;
    const int r0 = lane >> 2, kb = (lane & 3) * 4;
    const int m = mtile * 128 + mw * 32 + mt * 16 + r0;
    const int k = ks * 64 + kk * 32 + kb;

    const float4* x0 = reinterpret_cast<const float4*>(x + (size_t)m * K_TOTAL + k);
    const float4* x8 = reinterpret_cast<const float4*>(x + (size_t)(m + 8) * K_TOTAL + k);
    float4 v00 = x0[0], v01 = x0[4];   // k..k+3, k+16..k+19 (row r0)
    float4 v10 = x8[0], v11 = x8[4];   // same, row r0+8

    uint4 H, L;
    cvt4(v00, H.x, L.x);
    cvt4(v10, H.y, L.y);
    cvt4(v01, H.z, L.z);
    cvt4(v11, H.w, L.w);

    unsigned char* base = g_A + (((size_t)(mtile * NUM_KS + ks)) << 14) + ((size_t)fl << 4);
    *reinterpret_cast<uint4*>(base)        = H;   // h plane
    *reinterpret_cast<uint4*>(base + 8192) = L;   // l plane
}

// ---------------------------------------------------------------------------
// pack_b: wq int32 -> s8 in mma B-fragment order.
// B chunk (ntile, ks): 1024 slots x 8B; slot
//   fl = ((nw*2+kk)*8+nt)*32 + lane ; bytes: [n=c0, k0..3][n=c0, k16..19]
//   c0 = lane>>2, k0 = kchunk + kk*32 + (lane&3)*4.
// ---------------------------------------------------------------------------
__global__ void __launch_bounds__(256) pack_b_kernel(const int* __restrict__ wq) {
    const int t = blockIdx.x * 256 + threadIdx.x;     // 2,097,152 threads
    const int ntile = t >> 16;
    const int rem   = t & 65535;
    const int ks    = rem >> 10;
    const int fl    = rem & 1023;
    const int nw = fl >> 9, kk = (fl >> 8) & 1, nt = (fl >> 5) & 7, lane = fl & 31;
    const int c0 = lane >> 2, kb = (lane & 3) * 4;
    const int n = ntile * 128 + nw * 64 + nt * 8 + c0;
    const int k = ks * 64 + kk * 32 + kb;

    const int4* w0 = reinterpret_cast<const int4*>(wq + (size_t)n * K_TOTAL + k);
    int4 a = w0[0], b = w0[4];   // k..k+3 ; k+16..k+19
    uint32_t p0 = (uint32_t)(a.x & 0xFF) | ((uint32_t)(a.y & 0xFF) << 8) |
                  ((uint32_t)(a.z & 0xFF) << 16) | ((uint32_t)(a.w & 0xFF) << 24);
    uint32_t p1 = (uint32_t)(b.x & 0xFF) | ((uint32_t)(b.y & 0xFF) << 8) |
                  ((uint32_t)(b.z & 0xFF) << 16) | ((uint32_t)(b.w & 0xFF) << 24);

    uint2 v = make_uint2(p0, p1);
    *reinterpret_cast<uint2*>(g_B + (((size_t)(ntile * NUM_KS + ks)) << 13) + ((size_t)fl << 3)) = v;
}

// ---------------------------------------------------------------------------
// GEMM: CTA 128x128, 256 thr = 8 warps (4m x 2n), warp tile 32x64.
// ---------------------------------------------------------------------------
__global__ void __launch_bounds__(256, 1) qgemm_kernel(
    const float* __restrict__ scale_p,
    const float* __restrict__ bias,
    float* __restrict__ out)
{
    extern __shared__ __align__(128) unsigned char smem[];
    const uint32_t sb = smem_u32(smem);
    const int tid = threadIdx.x, lane = tid & 31, warp = tid >> 5;
    const int mw = warp & 3, nw = warp >> 2;
    const int ntile = blockIdx.x, mtile = blockIdx.y;

    if (tid < STAGES) MBARRIER_INIT(sb + tid * 8, 1);
    float* sbias = reinterpret_cast<float*>(smem + SMEM_BIAS);
    if (tid < 128) sbias[tid] = bias[ntile * 128 + tid];
    const float qs = scale_p[0] * (1.0f / 2048.0f);
    __syncthreads();

    // prologue: fill stages 0..STAGES-2
    if (tid == 0) {
#pragma unroll
        for (int s = 0; s < STAGES - 1; s++) {
            const uint32_t mbar = sb + s * 8;
            const uint32_t dst  = sb + SMEM_STAGE0 + s * STAGE_BYTES;
            MBARRIER_EXPECT_TX(mbar, STAGE_BYTES);
            bulk_g2s(dst, g_A + (((size_t)(mtile * NUM_KS + s)) << 14), A_CHUNK_BYTES, mbar);
            bulk_g2s(dst + A_CHUNK_BYTES, g_B + (((size_t)(ntile * NUM_KS + s)) << 13),
                     B_CHUNK_BYTES, mbar);
        }
    }

    int acc[2][2][8][4];
#pragma unroll
    for (int p = 0; p < 2; p++)
#pragma unroll
        for (int mt = 0; mt < 2; mt++)
#pragma unroll
            for (int nt = 0; nt < 8; nt++)
#pragma unroll
                for (int j = 0; j < 4; j++) acc[p][mt][nt][j] = 0;

    for (int ks = 0; ks < NUM_KS; ks++) {
        const int s = ks % STAGES;
        MBARRIER_WAIT_PARITY(sb + s * 8, (ks / STAGES) & 1);
        const unsigned char* st = smem + SMEM_STAGE0 + s * STAGE_BYTES;

#pragma unroll
        for (int kk = 0; kk < 2; kk++) {
            uint32_t afr[2][2][4];
            uint32_t bfr[8][2];
#pragma unroll
            for (int p = 0; p < 2; p++)
#pragma unroll
                for (int mt = 0; mt < 2; mt++) {
                    const uint4 v = *reinterpret_cast<const uint4*>(
                        st + p * 8192 + (((((mw * 2 + kk) * 2 + mt) * 32) + lane) << 4));
                    afr[p][mt][0] = v.x; afr[p][mt][1] = v.y;
                    afr[p][mt][2] = v.z; afr[p][mt][3] = v.w;
                }
#pragma unroll
            for (int nt = 0; nt < 8; nt++) {
                const uint2 v = *reinterpret_cast<const uint2*>(
                    st + A_CHUNK_BYTES + (((((nw * 2 + kk) * 8 + nt) * 32) + lane) << 3));
                bfr[nt][0] = v.x; bfr[nt][1] = v.y;
            }
#pragma unroll
            for (int p = 0; p < 2; p++)
#pragma unroll
                for (int mt = 0; mt < 2; mt++)
#pragma unroll
                    for (int nt = 0; nt < 8; nt++)
                        mma_s8(acc[p][mt][nt], afr[p][mt], bfr[nt]);
        }

        __syncthreads();   // everyone done with slot (ks-1)%STAGES -> safe to refill
        if (tid == 0 && ks + STAGES - 1 < NUM_KS) {
            const int ks2 = ks + STAGES - 1;
            const int s2 = ks2 % STAGES;
            const uint32_t mbar = sb + s2 * 8;
            const uint32_t dst  = sb + SMEM_STAGE0 + s2 * STAGE_BYTES;
            MBARRIER_EXPECT_TX(mbar, STAGE_BYTES);
            bulk_g2s(dst, g_A + (((size_t)(mtile * NUM_KS + ks2)) << 14), A_CHUNK_BYTES, mbar);
            bulk_g2s(dst + A_CHUNK_BYTES, g_B + (((size_t)(ntile * NUM_KS + ks2)) << 13),
                     B_CHUNK_BYTES, mbar);
        }
    }

    // ------------------------------ epilogue ------------------------------
    // combine planes, scale+bias, stage through SMEM (pitch 136 f), coalesced out
    float* stg = reinterpret_cast<float*>(smem + SMEM_STAGE0);
    const int r0 = mw * 32 + (lane >> 2);
    const int cb = nw * 64 + (lane & 3) * 2;

#pragma unroll
    for (int mt = 0; mt < 2; mt++)
#pragma unroll
        for (int nt = 0; nt < 8; nt++) {
            const int row = r0 + mt * 16;
            const int col = cb + nt * 8;
            const int v0 = acc[0][mt][nt][0] * 128 + acc[1][mt][nt][0];
            const int v1 = acc[0][mt][nt][1] * 128 + acc[1][mt][nt][1];
            const int v2 = acc[0][mt][nt][2] * 128 + acc[1][mt][nt][2];
            const int v3 = acc[0][mt][nt][3] * 128 + acc[1][mt][nt][3];
            float2 lo = make_float2((float)v0 * qs + sbias[col],
                                    (float)v1 * qs + sbias[col + 1]);
            float2 hi = make_float2((float)v2 * qs + sbias[col],
                                    (float)v3 * qs + sbias[col + 1]);
            *reinterpret_cast<float2*>(stg + row * 136 + col)       = lo;
            *reinterpret_cast<float2*>(stg + (row + 8) * 136 + col) = hi;
        }
    __syncthreads();

    const float4* s4 = reinterpret_cast<const float4*>(stg);
    float4* o4 = reinterpret_cast<float4*>(out);
#pragma unroll
    for (int i = 0; i < 16; i++) {
        const int idx = tid + i * 256;
        const int r = idx >> 5, c4 = idx & 31;
        o4[(size_t)(mtile * 128 + r) * (N_TOTAL / 4) + ntile * 32 + c4] = s4[r * 34 + c4];
    }
}

// ---------------------------------------------------------------------------
extern "C" void kernel_launch(void* const* d_in, const int* in_sizes, int n_in,
                              void* d_out, int out_size) {
    const float* x     = (const float*)d_in[0];
    const int*   wq    = (const int*)d_in[1];
    const float* scale = (const float*)d_in[2];
    const float* bias  = (const float*)d_in[3];
    float* out = (float*)d_out;

    pack_a_kernel<<<16384, 256>>>(x);
    pack_b_kernel<<<8192, 256>>>(wq);

    cudaFuncSetAttribute(qgemm_kernel,
                         cudaFuncAttributeMaxDynamicSharedMemorySize, DYN_SMEM);
    dim3 grid(NUM_NT, NUM_MT);   // ntile fast: wave shares A rows, B resident in L2
    qgemm_kernel<<<grid, 256, DYN_SMEM>>>(scale, bias, out);
}

// round 3
// speedup vs baseline: 5.1008x; 5.1008x over previous
#include <cuda_runtime.h>
#include <cuda_fp16.h>
#include <cstdint>

// ============================================================================
// QuantizedLinear, sm_103 base-PTX build (no tcgen05 in this toolchain).
// R2 showed classic s8 mma.sync is ALU-EMULATED (~58cyc/op) -> 7.3ms at the
// dp4a roofline. R3 pivots to classic fp16 HMMA (native "fallback HMMA" path
// per sm_103a docs), SINGLE fp16 plane:
//   x -> fp16 (rel sigma ~1.7e-4, aggregate-norm metric -> passes 1e-3)
//   wq (0..126) -> fp16 exact
//   y = (x_h @ w_h^T) * scale + bias, fp32 accumulate in mma.
// Work halves vs R2's two planes. Packing is mma-fragment-ordered so the GEMM
// does only linear conflict-free LDS.128/LDS.64.
// Packs fused into ONE kernel so ncu (-s 5 -c 1, 2 launches/replay) captures
// the GEMM next round.
// ============================================================================

#define M_TOTAL 16384
#define N_TOTAL 4096
#define K_TOTAL 4096
#define NUM_KS  64            // K chunks of 64
#define NUM_MT  128           // M tiles of 128
#define NUM_NT  32            // N tiles of 128
#define STAGES  6

#define A_CHUNK_BYTES 16384   // 128m x 64k fp16, frag-ordered
#define B_CHUNK_BYTES 16384   // 128n x 64k fp16, frag-ordered
#define STAGE_BYTES   (A_CHUNK_BYTES + B_CHUNK_BYTES)   // 32768

#define SMEM_BIAS   512
#define SMEM_STAGE0 1024
#define DYN_SMEM    (SMEM_STAGE0 + STAGES * STAGE_BYTES)  // 197632

__device__ __align__(1024) unsigned char g_A[(size_t)NUM_MT * NUM_KS * A_CHUNK_BYTES]; // 128 MB
__device__ __align__(1024) unsigned char g_B[(size_t)NUM_NT * NUM_KS * B_CHUNK_BYTES]; //  32 MB

// ---------------------------------------------------------------------------
__device__ __forceinline__ uint32_t smem_u32(const void* p) {
    uint32_t a;
    asm("{ .reg .u64 t; cvta.to.shared.u64 t, %1; cvt.u32.u64 %0, t; }" : "=r"(a) : "l"(p));
    return a;
}

#define MBARRIER_INIT(addr, cnt) \
    asm volatile("mbarrier.init.shared.b64 [%0], %1;" :: "r"((uint32_t)(addr)), "r"((uint32_t)(cnt)) : "memory")
#define MBARRIER_EXPECT_TX(addr, bytes) \
    asm volatile("mbarrier.arrive.expect_tx.shared.b64 _, [%0], %1;" :: "r"((uint32_t)(addr)), "r"((uint32_t)(bytes)) : "memory")

#define MBARRIER_WAIT_PARITY(addr, parity) do {                                   \
    uint32_t _m = (uint32_t)(addr); uint32_t _p = (uint32_t)(parity); uint32_t _d;\
    asm volatile("{\n\t.reg .pred p;\n\t"                                         \
        "mbarrier.try_wait.parity.acquire.cta.shared::cta.b64 p, [%1], %2;\n\t"   \
        "selp.b32 %0, 1, 0, p;\n\t}"                                              \
        : "=r"(_d) : "r"(_m), "r"(_p) : "memory");                                \
    if (!_d) {                                                                    \
        asm volatile("{\n\t.reg .pred P1;\n\t"                                    \
            "WAIT_LOOP_%=:\n\t"                                                   \
            "mbarrier.try_wait.parity.acquire.cta.shared::cta.b64 P1, [%0], %1, 0x989680;\n\t" \
            "@P1 bra.uni WAIT_DONE_%=;\n\t"                                       \
            "bra.uni WAIT_LOOP_%=;\n\t"                                           \
            "WAIT_DONE_%=:\n\t}"                                                  \
            :: "r"(_m), "r"(_p) : "memory");                                      \
    }                                                                             \
} while (0)

__device__ __forceinline__ void bulk_g2s(uint32_t dst, const void* src,
                                         uint32_t bytes, uint32_t mbar) {
    asm volatile(
        "cp.async.bulk.shared::cluster.global.mbarrier::complete_tx::bytes [%0], [%1], %2, [%3];"
        :: "r"(dst), "l"(src), "r"(bytes), "r"(mbar) : "memory");
}

// fp16 HMMA: D(f32, m16n8) += A(f16, m16k16) * B(f16, k16n8)
__device__ __forceinline__ void mma_f16(float* d, const uint32_t* a, const uint32_t* b) {
    asm volatile(
        "mma.sync.aligned.m16n8k16.row.col.f32.f16.f16.f32 "
        "{%0,%1,%2,%3}, {%4,%5,%6,%7}, {%8,%9}, {%0,%1,%2,%3};"
        : "+f"(d[0]), "+f"(d[1]), "+f"(d[2]), "+f"(d[3])
        : "r"(a[0]), "r"(a[1]), "r"(a[2]), "r"(a[3]), "r"(b[0]), "r"(b[1]));
}

__device__ __forceinline__ uint32_t h2(float a, float b) {
    __half2 h = __floats2half2_rn(a, b);
    return *reinterpret_cast<uint32_t*>(&h);
}

// ---------------------------------------------------------------------------
// Fused pack kernel.
//  A-part (blocks 0..32767): x fp32 -> fp16 frags.
//    chunk (mtile,ks) = 1024 slots x 16B. slot = ((mw*4+kk)*2+mt)*32 + lane.
//    frag: a0=(r0,k0,k0+1) a1=(r0+8,..) a2=(r0,k0+8,9) a3=(r0+8,k0+8,9)
//    with r0=lane>>2, k0 = ks*64 + kk*16 + (lane&3)*2, m0=mtile*128+mw*32+mt*16.
//  B-part (blocks 32768..49151): wq int32 -> fp16 frags (exact, 0..126).
//    chunk (ntile,ks) = 2048 slots x 8B. slot = ((nw*4+kk)*8+nt)*32 + lane.
//    frag: b0=(c0,k0,k0+1) b1=(c0,k0+8,9), c0 = ntile*128+nw*64+nt*8+(lane>>2).
// ---------------------------------------------------------------------------
__global__ void __launch_bounds__(256) pack_kernel(const float* __restrict__ x,
                                                   const int* __restrict__ wq) {
    if (blockIdx.x < 32768) {
        const int t = blockIdx.x * 256 + threadIdx.x;
        const int chunk = t >> 10, slot = t & 1023;
        const int mtile = chunk >> 6, ks = chunk & 63;
        const int lane = slot & 31, mt = (slot >> 5) & 1, kk = (slot >> 6) & 3, mw = slot >> 8;
        const int m0 = mtile * 128 + mw * 32 + mt * 16 + (lane >> 2);
        const int kb = ks * 64 + kk * 16 + (lane & 3) * 2;
        const float* p0 = x + (size_t)m0 * K_TOTAL + kb;
        const float* p8 = p0 + 8 * K_TOTAL;
        const float2 f00 = *reinterpret_cast<const float2*>(p0);
        const float2 f10 = *reinterpret_cast<const float2*>(p8);
        const float2 f01 = *reinterpret_cast<const float2*>(p0 + 8);
        const float2 f11 = *reinterpret_cast<const float2*>(p8 + 8);
        uint4 v;
        v.x = h2(f00.x, f00.y);
        v.y = h2(f10.x, f10.y);
        v.z = h2(f01.x, f01.y);
        v.w = h2(f11.x, f11.y);
        *reinterpret_cast<uint4*>(g_A + ((size_t)chunk << 14) + ((size_t)slot << 4)) = v;
    } else {
        const int t = (blockIdx.x - 32768) * 256 + threadIdx.x;
        const int chunk = t >> 11, slot = t & 2047;
        const int ntile = chunk >> 6, ks = chunk & 63;
        const int lane = slot & 31, nt = (slot >> 5) & 7, kk = (slot >> 8) & 3, nw = slot >> 10;
        const int n0 = ntile * 128 + nw * 64 + nt * 8 + (lane >> 2);
        const int kb = ks * 64 + kk * 16 + (lane & 3) * 2;
        const int* q0 = wq + (size_t)n0 * K_TOTAL + kb;
        const int2 w0 = *reinterpret_cast<const int2*>(q0);
        const int2 w1 = *reinterpret_cast<const int2*>(q0 + 8);
        uint2 v;
        v.x = h2((float)w0.x, (float)w0.y);
        v.y = h2((float)w1.x, (float)w1.y);
        *reinterpret_cast<uint2*>(g_B + ((size_t)chunk << 14) + ((size_t)slot << 3)) = v;
    }
}

// ---------------------------------------------------------------------------
// GEMM: CTA 128x128, 256 thr = 8 warps (4m x 2n), warp tile 32x64.
// 6-stage cp.async.bulk pipeline; single-thread producer; per-chunk barrier.
// ---------------------------------------------------------------------------
__global__ void __launch_bounds__(256, 1) qgemm_kernel(
    const float* __restrict__ scale_p,
    const float* __restrict__ bias,
    float* __restrict__ out)
{
    extern __shared__ __align__(128) unsigned char smem[];
    const uint32_t sb = smem_u32(smem);
    const int tid = threadIdx.x, lane = tid & 31, warp = tid >> 5;
    const int mw = warp & 3, nw = warp >> 2;
    const int ntile = blockIdx.x, mtile = blockIdx.y;

    if (tid < STAGES) MBARRIER_INIT(sb + tid * 8, 1);
    float* sbias = reinterpret_cast<float*>(smem + SMEM_BIAS);
    if (tid < 128) sbias[tid] = bias[ntile * 128 + tid];
    const float qs = scale_p[0];
    __syncthreads();

    if (tid == 0) {
#pragma unroll
        for (int s = 0; s < STAGES - 1; s++) {
            const uint32_t mbar = sb + s * 8;
            const uint32_t dst  = sb + SMEM_STAGE0 + s * STAGE_BYTES;
            MBARRIER_EXPECT_TX(mbar, STAGE_BYTES);
            bulk_g2s(dst, g_A + (((size_t)(mtile * NUM_KS + s)) << 14), A_CHUNK_BYTES, mbar);
            bulk_g2s(dst + A_CHUNK_BYTES,
                     g_B + (((size_t)(ntile * NUM_KS + s)) << 14), B_CHUNK_BYTES, mbar);
        }
    }

    float acc[2][8][4];
#pragma unroll
    for (int mt = 0; mt < 2; mt++)
#pragma unroll
        for (int nt = 0; nt < 8; nt++)
#pragma unroll
            for (int j = 0; j < 4; j++) acc[mt][nt][j] = 0.0f;

    for (int ks = 0; ks < NUM_KS; ks++) {
        const int s = ks % STAGES;
        MBARRIER_WAIT_PARITY(sb + s * 8, (ks / STAGES) & 1);
        const unsigned char* st = smem + SMEM_STAGE0 + s * STAGE_BYTES;

#pragma unroll
        for (int kk = 0; kk < 4; kk++) {
            uint32_t afr[2][4];
            uint32_t bfr[8][2];
#pragma unroll
            for (int mt = 0; mt < 2; mt++) {
                const uint4 v = *reinterpret_cast<const uint4*>(
                    st + ((((mw * 4 + kk) * 2 + mt) * 32 + lane) << 4));
                afr[mt][0] = v.x; afr[mt][1] = v.y; afr[mt][2] = v.z; afr[mt][3] = v.w;
            }
#pragma unroll
            for (int nt = 0; nt < 8; nt++) {
                const uint2 v = *reinterpret_cast<const uint2*>(
                    st + A_CHUNK_BYTES + ((((nw * 4 + kk) * 8 + nt) * 32 + lane) << 3));
                bfr[nt][0] = v.x; bfr[nt][1] = v.y;
            }
#pragma unroll
            for (int mt = 0; mt < 2; mt++)
#pragma unroll
                for (int nt = 0; nt < 8; nt++)
                    mma_f16(acc[mt][nt], afr[mt], bfr[nt]);
        }

        __syncthreads();   // all warps done with stage (ks-1)%STAGES -> refillable
        if (tid == 0 && ks + STAGES - 1 < NUM_KS) {
            const int ks2 = ks + STAGES - 1;
            const int s2 = ks2 % STAGES;
            const uint32_t mbar = sb + s2 * 8;
            const uint32_t dst  = sb + SMEM_STAGE0 + s2 * STAGE_BYTES;
            MBARRIER_EXPECT_TX(mbar, STAGE_BYTES);
            bulk_g2s(dst, g_A + (((size_t)(mtile * NUM_KS + ks2)) << 14), A_CHUNK_BYTES, mbar);
            bulk_g2s(dst + A_CHUNK_BYTES,
                     g_B + (((size_t)(ntile * NUM_KS + ks2)) << 14), B_CHUNK_BYTES, mbar);
        }
    }

    // ------------------------------ epilogue ------------------------------
    float* stg = reinterpret_cast<float*>(smem + SMEM_STAGE0);   // 128 x 136 f
    const int r0 = mw * 32 + (lane >> 2);
    const int cb = nw * 64 + (lane & 3) * 2;

#pragma unroll
    for (int mt = 0; mt < 2; mt++)
#pragma unroll
        for (int nt = 0; nt < 8; nt++) {
            const int row = r0 + mt * 16;
            const int col = cb + nt * 8;
            float2 lo = make_float2(acc[mt][nt][0] * qs + sbias[col],
                                    acc[mt][nt][1] * qs + sbias[col + 1]);
            float2 hi = make_float2(acc[mt][nt][2] * qs + sbias[col],
                                    acc[mt][nt][3] * qs + sbias[col + 1]);
            *reinterpret_cast<float2*>(stg + row * 136 + col)       = lo;
            *reinterpret_cast<float2*>(stg + (row + 8) * 136 + col) = hi;
        }
    __syncthreads();

    const float4* s4 = reinterpret_cast<const float4*>(stg);
    float4* o4 = reinterpret_cast<float4*>(out);
#pragma unroll
    for (int i = 0; i < 16; i++) {
        const int idx = tid + i * 256;
        const int r = idx >> 5, c4 = idx & 31;
        o4[(size_t)(mtile * 128 + r) * (N_TOTAL / 4) + ntile * 32 + c4] = s4[r * 34 + c4];
    }
}

// ---------------------------------------------------------------------------
extern "C" void kernel_launch(void* const* d_in, const int* in_sizes, int n_in,
                              void* d_out, int out_size) {
    const float* x     = (const float*)d_in[0];
    const int*   wq    = (const int*)d_in[1];
    const float* scale = (const float*)d_in[2];
    const float* bias  = (const float*)d_in[3];
    float* out = (float*)d_out;

    // fused pack: 32768 A-blocks + 16384 B-blocks
    pack_kernel<<<49152, 256>>>(x, wq);

    cudaFuncSetAttribute(qgemm_kernel,
                         cudaFuncAttributeMaxDynamicSharedMemorySize, DYN_SMEM);
    dim3 grid(NUM_NT, NUM_MT);   // ntile fast: wave shares A rows, B L2-resident
    qgemm_kernel<<<grid, 256, DYN_SMEM>>>(scale, bias, out);
}

// round 5
// speedup vs baseline: 5.7743x; 1.1320x over previous
#include <cuda_runtime.h>
#include <cuda_fp16.h>
#include <cstdint>

// ============================================================================
// QuantizedLinear, sm_103 base-PTX build (no tcgen05 in this toolchain).
// R3: classic fp16 HMMA is NATIVE (tensor=66.5%) -> 1437us. Limit was
// occupancy: 197KB smem forced 1 CTA/SM (2 warps/SMSP) -> latency bubbles.
// R4: 3 stages (99KB dyn smem) + __launch_bounds__(256,2) -> 2 CTAs/SM,
// 4 warps/SMSP. Everything else unchanged.
//   x -> fp16 (rel sigma ~1.7e-4), wq (0..126) -> fp16 exact,
//   y = (x_h @ w_h^T)*scale + bias, fp32 accum.
// ============================================================================

#define M_TOTAL 16384
#define N_TOTAL 4096
#define K_TOTAL 4096
#define NUM_KS  64            // K chunks of 64
#define NUM_MT  128           // M tiles of 128
#define NUM_NT  32            // N tiles of 128
#define STAGES  3

#define A_CHUNK_BYTES 16384   // 128m x 64k fp16, frag-ordered
#define B_CHUNK_BYTES 16384   // 128n x 64k fp16, frag-ordered
#define STAGE_BYTES   (A_CHUNK_BYTES + B_CHUNK_BYTES)   // 32768

#define SMEM_BIAS   512
#define SMEM_STAGE0 1024
#define DYN_SMEM    (SMEM_STAGE0 + STAGES * STAGE_BYTES)  // 99328 -> 2 CTAs/SM

__device__ __align__(1024) unsigned char g_A[(size_t)NUM_MT * NUM_KS * A_CHUNK_BYTES]; // 128 MB
__device__ __align__(1024) unsigned char g_B[(size_t)NUM_NT * NUM_KS * B_CHUNK_BYTES]; //  32 MB

// ---------------------------------------------------------------------------
__device__ __forceinline__ uint32_t smem_u32(const void* p) {
    uint32_t a;
    asm("{ .reg .u64 t; cvta.to.shared.u64 t, %1; cvt.u32.u64 %0, t; }" : "=r"(a) : "l"(p));
    return a;
}

#define MBARRIER_INIT(addr, cnt) \
    asm volatile("mbarrier.init.shared.b64 [%0], %1;" :: "r"((uint32_t)(addr)), "r"((uint32_t)(cnt)) : "memory")
#define MBARRIER_EXPECT_TX(addr, bytes) \
    asm volatile("mbarrier.arrive.expect_tx.shared.b64 _, [%0], %1;" :: "r"((uint32_t)(addr)), "r"((uint32_t)(bytes)) : "memory")

#define MBARRIER_WAIT_PARITY(addr, parity) do {                                   \
    uint32_t _m = (uint32_t)(addr); uint32_t _p = (uint32_t)(parity); uint32_t _d;\
    asm volatile("{\n\t.reg .pred p;\n\t"                                         \
        "mbarrier.try_wait.parity.acquire.cta.shared::cta.b64 p, [%1], %2;\n\t"   \
        "selp.b32 %0, 1, 0, p;\n\t}"                                              \
        : "=r"(_d) : "r"(_m), "r"(_p) : "memory");                                \
    if (!_d) {                                                                    \
        asm volatile("{\n\t.reg .pred P1;\n\t"                                    \
            "WAIT_LOOP_%=:\n\t"                                                   \
            "mbarrier.try_wait.parity.acquire.cta.shared::cta.b64 P1, [%0], %1, 0x989680;\n\t" \
            "@P1 bra.uni WAIT_DONE_%=;\n\t"                                       \
            "bra.uni WAIT_LOOP_%=;\n\t"                                           \
            "WAIT_DONE_%=:\n\t}"                                                  \
            :: "r"(_m), "r"(_p) : "memory");                                      \
    }                                                                             \
} while (0)

__device__ __forceinline__ void bulk_g2s(uint32_t dst, const void* src,
                                         uint32_t bytes, uint32_t mbar) {
    asm volatile(
        "cp.async.bulk.shared::cluster.global.mbarrier::complete_tx::bytes [%0], [%1], %2, [%3];"
        :: "r"(dst), "l"(src), "r"(bytes), "r"(mbar) : "memory");
}

// fp16 HMMA: D(f32, m16n8) += A(f16, m16k16) * B(f16, k16n8)
__device__ __forceinline__ void mma_f16(float* d, const uint32_t* a, const uint32_t* b) {
    asm volatile(
        "mma.sync.aligned.m16n8k16.row.col.f32.f16.f16.f32 "
        "{%0,%1,%2,%3}, {%4,%5,%6,%7}, {%8,%9}, {%0,%1,%2,%3};"
        : "+f"(d[0]), "+f"(d[1]), "+f"(d[2]), "+f"(d[3])
        : "r"(a[0]), "r"(a[1]), "r"(a[2]), "r"(a[3]), "r"(b[0]), "r"(b[1]));
}

__device__ __forceinline__ uint32_t h2(float a, float b) {
    __half2 h = __floats2half2_rn(a, b);
    return *reinterpret_cast<uint32_t*>(&h);
}

// ---------------------------------------------------------------------------
// Fused pack kernel (A-part: 32768 blocks, B-part: 16384 blocks).
// ---------------------------------------------------------------------------
__global__ void __launch_bounds__(256) pack_kernel(const float* __restrict__ x,
                                                   const int* __restrict__ wq) {
    if (blockIdx.x < 32768) {
        const int t = blockIdx.x * 256 + threadIdx.x;
        const int chunk = t >> 10, slot = t & 1023;
        const int mtile = chunk >> 6, ks = chunk & 63;
        const int lane = slot & 31, mt = (slot >> 5) & 1, kk = (slot >> 6) & 3, mw = slot >> 8;
        const int m0 = mtile * 128 + mw * 32 + mt * 16 + (lane >> 2);
        const int kb = ks * 64 + kk * 16 + (lane & 3) * 2;
        const float* p0 = x + (size_t)m0 * K_TOTAL + kb;
        const float* p8 = p0 + 8 * K_TOTAL;
        const float2 f00 = *reinterpret_cast<const float2*>(p0);
        const float2 f10 = *reinterpret_cast<const float2*>(p8);
        const float2 f01 = *reinterpret_cast<const float2*>(p0 + 8);
        const float2 f11 = *reinterpret_cast<const float2*>(p8 + 8);
        uint4 v;
        v.x = h2(f00.x, f00.y);
        v.y = h2(f10.x, f10.y);
        v.z = h2(f01.x, f01.y);
        v.w = h2(f11.x, f11.y);
        *reinterpret_cast<uint4*>(g_A + ((size_t)chunk << 14) + ((size_t)slot << 4)) = v;
    } else {
        const int t = (blockIdx.x - 32768) * 256 + threadIdx.x;
        const int chunk = t >> 11, slot = t & 2047;
        const int ntile = chunk >> 6, ks = chunk & 63;
        const int lane = slot & 31, nt = (slot >> 5) & 7, kk = (slot >> 8) & 3, nw = slot >> 10;
        const int n0 = ntile * 128 + nw * 64 + nt * 8 + (lane >> 2);
        const int kb = ks * 64 + kk * 16 + (lane & 3) * 2;
        const int* q0 = wq + (size_t)n0 * K_TOTAL + kb;
        const int2 w0 = *reinterpret_cast<const int2*>(q0);
        const int2 w1 = *reinterpret_cast<const int2*>(q0 + 8);
        uint2 v;
        v.x = h2((float)w0.x, (float)w0.y);
        v.y = h2((float)w1.x, (float)w1.y);
        *reinterpret_cast<uint2*>(g_B + ((size_t)chunk << 14) + ((size_t)slot << 3)) = v;
    }
}

// ---------------------------------------------------------------------------
// GEMM: CTA 128x128, 256 thr = 8 warps (4m x 2n), warp tile 32x64.
// 3-stage cp.async.bulk pipeline; 2 CTAs/SM for latency hiding.
// ---------------------------------------------------------------------------
__global__ void __launch_bounds__(256, 2) qgemm_kernel(
    const float* __restrict__ scale_p,
    const float* __restrict__ bias,
    float* __restrict__ out)
{
    extern __shared__ __align__(128) unsigned char smem[];
    const uint32_t sb = smem_u32(smem);
    const int tid = threadIdx.x, lane = tid & 31, warp = tid >> 5;
    const int mw = warp & 3, nw = warp >> 2;
    const int ntile = blockIdx.x, mtile = blockIdx.y;

    if (tid < STAGES) MBARRIER_INIT(sb + tid * 8, 1);
    float* sbias = reinterpret_cast<float*>(smem + SMEM_BIAS);
    if (tid < 128) sbias[tid] = bias[ntile * 128 + tid];
    const float qs = scale_p[0];
    __syncthreads();

    if (tid == 0) {
#pragma unroll
        for (int s = 0; s < STAGES - 1; s++) {
            const uint32_t mbar = sb + s * 8;
            const uint32_t dst  = sb + SMEM_STAGE0 + s * STAGE_BYTES;
            MBARRIER_EXPECT_TX(mbar, STAGE_BYTES);
            bulk_g2s(dst, g_A + (((size_t)(mtile * NUM_KS + s)) << 14), A_CHUNK_BYTES, mbar);
            bulk_g2s(dst + A_CHUNK_BYTES,
                     g_B + (((size_t)(ntile * NUM_KS + s)) << 14), B_CHUNK_BYTES, mbar);
        }
    }

    float acc[2][8][4];
#pragma unroll
    for (int mt = 0; mt < 2; mt++)
#pragma unroll
        for (int nt = 0; nt < 8; nt++)
#pragma unroll
            for (int j = 0; j < 4; j++) acc[mt][nt][j] = 0.0f;

    for (int ks = 0; ks < NUM_KS; ks++) {
        const int s = ks % STAGES;
        MBARRIER_WAIT_PARITY(sb + s * 8, (ks / STAGES) & 1);
        const unsigned char* st = smem + SMEM_STAGE0 + s * STAGE_BYTES;

#pragma unroll
        for (int kk = 0; kk < 4; kk++) {
            uint32_t afr[2][4];
            uint32_t bfr[8][2];
#pragma unroll
            for (int mt = 0; mt < 2; mt++) {
                const uint4 v = *reinterpret_cast<const uint4*>(
                    st + ((((mw * 4 + kk) * 2 + mt) * 32 + lane) << 4));
                afr[mt][0] = v.x; afr[mt][1] = v.y; afr[mt][2] = v.z; afr[mt][3] = v.w;
            }
#pragma unroll
            for (int nt = 0; nt < 8; nt++) {
                const uint2 v = *reinterpret_cast<const uint2*>(
                    st + A_CHUNK_BYTES + ((((nw * 4 + kk) * 8 + nt) * 32 + lane) << 3));
                bfr[nt][0] = v.x; bfr[nt][1] = v.y;
            }
#pragma unroll
            for (int mt = 0; mt < 2; mt++)
#pragma unroll
                for (int nt = 0; nt < 8; nt++)
                    mma_f16(acc[mt][nt], afr[mt], bfr[nt]);
        }

        __syncthreads();   // all warps done with this chunk -> oldest stage refillable
        if (tid == 0 && ks + STAGES - 1 < NUM_KS) {
            const int ks2 = ks + STAGES - 1;
            const int s2 = ks2 % STAGES;
            const uint32_t mbar = sb + s2 * 8;
            const uint32_t dst  = sb + SMEM_STAGE0 + s2 * STAGE_BYTES;
            MBARRIER_EXPECT_TX(mbar, STAGE_BYTES);
            bulk_g2s(dst, g_A + (((size_t)(mtile * NUM_KS + ks2)) << 14), A_CHUNK_BYTES, mbar);
            bulk_g2s(dst + A_CHUNK_BYTES,
                     g_B + (((size_t)(ntile * NUM_KS + ks2)) << 14), B_CHUNK_BYTES, mbar);
        }
    }

    // ------------------------------ epilogue ------------------------------
    float* stg = reinterpret_cast<float*>(smem + SMEM_STAGE0);   // 128 x 136 f
    const int r0 = mw * 32 + (lane >> 2);
    const int cb = nw * 64 + (lane & 3) * 2;

#pragma unroll
    for (int mt = 0; mt < 2; mt++)
#pragma unroll
        for (int nt = 0; nt < 8; nt++) {
            const int row = r0 + mt * 16;
            const int col = cb + nt * 8;
            float2 lo = make_float2(acc[mt][nt][0] * qs + sbias[col],
                                    acc[mt][nt][1] * qs + sbias[col + 1]);
            float2 hi = make_float2(acc[mt][nt][2] * qs + sbias[col],
                                    acc[mt][nt][3] * qs + sbias[col + 1]);
            *reinterpret_cast<float2*>(stg + row * 136 + col)       = lo;
            *reinterpret_cast<float2*>(stg + (row + 8) * 136 + col) = hi;
        }
    __syncthreads();

    const float4* s4 = reinterpret_cast<const float4*>(stg);
    float4* o4 = reinterpret_cast<float4*>(out);
#pragma unroll
    for (int i = 0; i < 16; i++) {
        const int idx = tid + i * 256;
        const int r = idx >> 5, c4 = idx & 31;
        o4[(size_t)(mtile * 128 + r) * (N_TOTAL / 4) + ntile * 32 + c4] = s4[r * 34 + c4];
    }
}

// ---------------------------------------------------------------------------
extern "C" void kernel_launch(void* const* d_in, const int* in_sizes, int n_in,
                              void* d_out, int out_size) {
    const float* x     = (const float*)d_in[0];
    const int*   wq    = (const int*)d_in[1];
    const float* scale = (const float*)d_in[2];
    const float* bias  = (const float*)d_in[3];
    float* out = (float*)d_out;

    pack_kernel<<<49152, 256>>>(x, wq);

    cudaFuncSetAttribute(qgemm_kernel,
                         cudaFuncAttributeMaxDynamicSharedMemorySize, DYN_SMEM);
    dim3 grid(NUM_NT, NUM_MT);   // ntile fast: wave shares A rows, B L2-resident
    qgemm_kernel<<<grid, 256, DYN_SMEM>>>(scale, bias, out);
}

// round 6
// speedup vs baseline: 6.5083x; 1.1271x over previous
#include <cuda_runtime.h>
#include <cuda_fp16.h>
#include <cstdint>

// ============================================================================
// QuantizedLinear, sm_103 base-PTX build (no tcgen05 in this toolchain).
// R3: classic fp16 HMMA native, 1437us @ 1 CTA/SM (tensor 66.5%).
// R4: 3 stages, 2 CTAs/SM -> 1269us (tensor 75.8%). Remaining bubbles =
//     per-chunk __syncthreads coupling all 8 warps 64x per CTA.
// R5: decoupled producer/consumer ring: per-stage empty mbarrier (count=8,
//     one arrive per warp), refill folded into warp0's loop (relaxed wait),
//     NO CTA barrier in the mainloop. Single __syncthreads before epilogue.
//   x -> fp16 (rel sigma ~1.7e-4), wq (0..126) -> fp16 exact,
//   y = (x_h @ w_h^T)*scale + bias, fp32 accum.  HMMA floor ~907us GEMM.
// ============================================================================

#define M_TOTAL 16384
#define N_TOTAL 4096
#define K_TOTAL 4096
#define NUM_KS  64            // K chunks of 64
#define NUM_MT  128           // M tiles of 128
#define NUM_NT  32            // N tiles of 128
#define STAGES  3

#define A_CHUNK_BYTES 16384   // 128m x 64k fp16, frag-ordered
#define B_CHUNK_BYTES 16384   // 128n x 64k fp16, frag-ordered
#define STAGE_BYTES   (A_CHUNK_BYTES + B_CHUNK_BYTES)   // 32768

#define SMEM_BIAS   512
#define SMEM_STAGE0 1024
#define DYN_SMEM    (SMEM_STAGE0 + STAGES * STAGE_BYTES)  // 99328 -> 2 CTAs/SM

__device__ __align__(1024) unsigned char g_A[(size_t)NUM_MT * NUM_KS * A_CHUNK_BYTES]; // 128 MB
__device__ __align__(1024) unsigned char g_B[(size_t)NUM_NT * NUM_KS * B_CHUNK_BYTES]; //  32 MB

// ---------------------------------------------------------------------------
__device__ __forceinline__ uint32_t smem_u32(const void* p) {
    uint32_t a;
    asm("{ .reg .u64 t; cvta.to.shared.u64 t, %1; cvt.u32.u64 %0, t; }" : "=r"(a) : "l"(p));
    return a;
}

#define MBARRIER_INIT(addr, cnt) \
    asm volatile("mbarrier.init.shared.b64 [%0], %1;" :: "r"((uint32_t)(addr)), "r"((uint32_t)(cnt)) : "memory")
#define MBARRIER_EXPECT_TX(addr, bytes) \
    asm volatile("mbarrier.arrive.expect_tx.shared.b64 _, [%0], %1;" :: "r"((uint32_t)(addr)), "r"((uint32_t)(bytes)) : "memory")
#define MBARRIER_ARRIVE(addr) \
    asm volatile("mbarrier.arrive.shared.b64 _, [%0];" :: "r"((uint32_t)(addr)) : "memory")

#define MBARRIER_WAIT_PARITY(addr, parity) do {                                   \
    uint32_t _m = (uint32_t)(addr); uint32_t _p = (uint32_t)(parity); uint32_t _d;\
    asm volatile("{\n\t.reg .pred p;\n\t"                                         \
        "mbarrier.try_wait.parity.acquire.cta.shared::cta.b64 p, [%1], %2;\n\t"   \
        "selp.b32 %0, 1, 0, p;\n\t}"                                              \
        : "=r"(_d) : "r"(_m), "r"(_p) : "memory");                                \
    if (!_d) {                                                                    \
        asm volatile("{\n\t.reg .pred P1;\n\t"                                    \
            "WAIT_LOOP_%=:\n\t"                                                   \
            "mbarrier.try_wait.parity.acquire.cta.shared::cta.b64 P1, [%0], %1, 0x989680;\n\t" \
            "@P1 bra.uni WAIT_DONE_%=;\n\t"                                       \
            "bra.uni WAIT_LOOP_%=;\n\t"                                           \
            "WAIT_DONE_%=:\n\t}"                                                  \
            :: "r"(_m), "r"(_p) : "memory");                                      \
    }                                                                             \
} while (0)

// relaxed wait: OK for producer whose post-wait smem writes are async-proxy (bulk DMA)
#define MBARRIER_WAIT_PARITY_RELAXED(addr, parity) do {                           \
    uint32_t _m = (uint32_t)(addr); uint32_t _p = (uint32_t)(parity); uint32_t _d;\
    asm volatile("{\n\t.reg .pred p;\n\t"                                         \
        "mbarrier.try_wait.parity.relaxed.cta.shared::cta.b64 p, [%1], %2;\n\t"   \
        "selp.b32 %0, 1, 0, p;\n\t}"                                              \
        : "=r"(_d) : "r"(_m), "r"(_p) : "memory");                                \
    if (!_d) {                                                                    \
        asm volatile("{\n\t.reg .pred P1;\n\t"                                    \
            "WAIT_LOOP_%=:\n\t"                                                   \
            "mbarrier.try_wait.parity.relaxed.cta.shared::cta.b64 P1, [%0], %1, 0x989680;\n\t" \
            "@P1 bra.uni WAIT_DONE_%=;\n\t"                                       \
            "bra.uni WAIT_LOOP_%=;\n\t"                                           \
            "WAIT_DONE_%=:\n\t}"                                                  \
            :: "r"(_m), "r"(_p) : "memory");                                      \
    }                                                                             \
} while (0)

__device__ __forceinline__ void bulk_g2s(uint32_t dst, const void* src,
                                         uint32_t bytes, uint32_t mbar) {
    asm volatile(
        "cp.async.bulk.shared::cluster.global.mbarrier::complete_tx::bytes [%0], [%1], %2, [%3];"
        :: "r"(dst), "l"(src), "r"(bytes), "r"(mbar) : "memory");
}

// fp16 HMMA: D(f32, m16n8) += A(f16, m16k16) * B(f16, k16n8)
__device__ __forceinline__ void mma_f16(float* d, const uint32_t* a, const uint32_t* b) {
    asm volatile(
        "mma.sync.aligned.m16n8k16.row.col.f32.f16.f16.f32 "
        "{%0,%1,%2,%3}, {%4,%5,%6,%7}, {%8,%9}, {%0,%1,%2,%3};"
        : "+f"(d[0]), "+f"(d[1]), "+f"(d[2]), "+f"(d[3])
        : "r"(a[0]), "r"(a[1]), "r"(a[2]), "r"(a[3]), "r"(b[0]), "r"(b[1]));
}

__device__ __forceinline__ uint32_t h2(float a, float b) {
    __half2 h = __floats2half2_rn(a, b);
    return *reinterpret_cast<uint32_t*>(&h);
}

// ---------------------------------------------------------------------------
// Fused pack kernel (A-part: 32768 blocks, B-part: 16384 blocks).
// ---------------------------------------------------------------------------
__global__ void __launch_bounds__(256) pack_kernel(const float* __restrict__ x,
                                                   const int* __restrict__ wq) {
    if (blockIdx.x < 32768) {
        const int t = blockIdx.x * 256 + threadIdx.x;
        const int chunk = t >> 10, slot = t & 1023;
        const int mtile = chunk >> 6, ks = chunk & 63;
        const int lane = slot & 31, mt = (slot >> 5) & 1, kk = (slot >> 6) & 3, mw = slot >> 8;
        const int m0 = mtile * 128 + mw * 32 + mt * 16 + (lane >> 2);
        const int kb = ks * 64 + kk * 16 + (lane & 3) * 2;
        const float* p0 = x + (size_t)m0 * K_TOTAL + kb;
        const float* p8 = p0 + 8 * K_TOTAL;
        const float2 f00 = *reinterpret_cast<const float2*>(p0);
        const float2 f10 = *reinterpret_cast<const float2*>(p8);
        const float2 f01 = *reinterpret_cast<const float2*>(p0 + 8);
        const float2 f11 = *reinterpret_cast<const float2*>(p8 + 8);
        uint4 v;
        v.x = h2(f00.x, f00.y);
        v.y = h2(f10.x, f10.y);
        v.z = h2(f01.x, f01.y);
        v.w = h2(f11.x, f11.y);
        *reinterpret_cast<uint4*>(g_A + ((size_t)chunk << 14) + ((size_t)slot << 4)) = v;
    } else {
        const int t = (blockIdx.x - 32768) * 256 + threadIdx.x;
        const int chunk = t >> 11, slot = t & 2047;
        const int ntile = chunk >> 6, ks = chunk & 63;
        const int lane = slot & 31, nt = (slot >> 5) & 7, kk = (slot >> 8) & 3, nw = slot >> 10;
        const int n0 = ntile * 128 + nw * 64 + nt * 8 + (lane >> 2);
        const int kb = ks * 64 + kk * 16 + (lane & 3) * 2;
        const int* q0 = wq + (size_t)n0 * K_TOTAL + kb;
        const int2 w0 = *reinterpret_cast<const int2*>(q0);
        const int2 w1 = *reinterpret_cast<const int2*>(q0 + 8);
        uint2 v;
        v.x = h2((float)w0.x, (float)w0.y);
        v.y = h2((float)w1.x, (float)w1.y);
        *reinterpret_cast<uint2*>(g_B + ((size_t)chunk << 14) + ((size_t)slot << 3)) = v;
    }
}

// ---------------------------------------------------------------------------
// GEMM: CTA 128x128, 256 thr = 8 warps (4m x 2n), warp tile 32x64.
// Decoupled ring: full[s] (count 1, tx-based) / empty[s] (count 8).
// Warp 0 lane 0 is the producer, folded into its own loop iteration.
// ---------------------------------------------------------------------------
__global__ void __launch_bounds__(256, 2) qgemm_kernel(
    const float* __restrict__ scale_p,
    const float* __restrict__ bias,
    float* __restrict__ out)
{
    extern __shared__ __align__(128) unsigned char smem[];
    const uint32_t sb = smem_u32(smem);
    const int tid = threadIdx.x, lane = tid & 31, warp = tid >> 5;
    const int mw = warp & 3, nw = warp >> 2;
    const int ntile = blockIdx.x, mtile = blockIdx.y;

    // mbarriers: full[s] @ sb + s*16, empty[s] @ sb + s*16 + 8
    if (tid < STAGES) {
        MBARRIER_INIT(sb + tid * 16, 1);        // full: tx-completion
        MBARRIER_INIT(sb + tid * 16 + 8, 8);    // empty: 8 warp arrivals
    }
    float* sbias = reinterpret_cast<float*>(smem + SMEM_BIAS);
    if (tid < 128) sbias[tid] = bias[ntile * 128 + tid];
    const float qs = scale_p[0];
    __syncthreads();

    const unsigned char* gA = g_A + (((size_t)mtile * NUM_KS) << 14);
    const unsigned char* gB = g_B + (((size_t)ntile * NUM_KS) << 14);

    // prologue: fill chunks 0..STAGES-2
    if (tid == 0) {
#pragma unroll
        for (int s = 0; s < STAGES - 1; s++) {
            const uint32_t mbar = sb + s * 16;
            const uint32_t dst  = sb + SMEM_STAGE0 + s * STAGE_BYTES;
            MBARRIER_EXPECT_TX(mbar, STAGE_BYTES);
            bulk_g2s(dst, gA + ((size_t)s << 14), A_CHUNK_BYTES, mbar);
            bulk_g2s(dst + A_CHUNK_BYTES, gB + ((size_t)s << 14), B_CHUNK_BYTES, mbar);
        }
    }

    float acc[2][8][4];
#pragma unroll
    for (int mt = 0; mt < 2; mt++)
#pragma unroll
        for (int nt = 0; nt < 8; nt++)
#pragma unroll
            for (int j = 0; j < 4; j++) acc[mt][nt][j] = 0.0f;

    for (int ks = 0; ks < NUM_KS; ks++) {
        const int s = ks % STAGES;

        // producer duty (warp 0 lane 0): refill chunk ks+STAGES-1 into its stage
        if (tid == 0) {
            const int ks2 = ks + STAGES - 1;
            if (ks2 < NUM_KS) {
                const int s2 = ks2 % STAGES;
                if (ks2 >= STAGES) {
                    // wait for the (ks2/STAGES - 1)-th consumption of stage s2
                    MBARRIER_WAIT_PARITY_RELAXED(sb + s2 * 16 + 8,
                                                 ((ks2 / STAGES) - 1) & 1);
                }
                const uint32_t mbar = sb + s2 * 16;
                const uint32_t dst  = sb + SMEM_STAGE0 + s2 * STAGE_BYTES;
                MBARRIER_EXPECT_TX(mbar, STAGE_BYTES);
                bulk_g2s(dst, gA + ((size_t)ks2 << 14), A_CHUNK_BYTES, mbar);
                bulk_g2s(dst + A_CHUNK_BYTES, gB + ((size_t)ks2 << 14),
                         B_CHUNK_BYTES, mbar);
            }
        }

        MBARRIER_WAIT_PARITY(sb + s * 16, (ks / STAGES) & 1);
        const unsigned char* st = smem + SMEM_STAGE0 + s * STAGE_BYTES;

#pragma unroll
        for (int kk = 0; kk < 4; kk++) {
            uint32_t afr[2][4];
            uint32_t bfr[8][2];
#pragma unroll
            for (int mt = 0; mt < 2; mt++) {
                const uint4 v = *reinterpret_cast<const uint4*>(
                    st + ((((mw * 4 + kk) * 2 + mt) * 32 + lane) << 4));
                afr[mt][0] = v.x; afr[mt][1] = v.y; afr[mt][2] = v.z; afr[mt][3] = v.w;
            }
#pragma unroll
            for (int nt = 0; nt < 8; nt++) {
                const uint2 v = *reinterpret_cast<const uint2*>(
                    st + A_CHUNK_BYTES + ((((nw * 4 + kk) * 8 + nt) * 32 + lane) << 3));
                bfr[nt][0] = v.x; bfr[nt][1] = v.y;
            }
#pragma unroll
            for (int mt = 0; mt < 2; mt++)
#pragma unroll
                for (int nt = 0; nt < 8; nt++)
                    mma_f16(acc[mt][nt], afr[mt], bfr[nt]);
        }

        // this warp is done with stage s
        if (lane == 0) MBARRIER_ARRIVE(sb + s * 16 + 8);
    }

    // ------------------------------ epilogue ------------------------------
    __syncthreads();   // stage buffers free (all warps past chunk 63)
    float* stg = reinterpret_cast<float*>(smem + SMEM_STAGE0);   // 128 x 136 f
    const int r0 = mw * 32 + (lane >> 2);
    const int cb = nw * 64 + (lane & 3) * 2;

#pragma unroll
    for (int mt = 0; mt < 2; mt++)
#pragma unroll
        for (int nt = 0; nt < 8; nt++) {
            const int row = r0 + mt * 16;
            const int col = cb + nt * 8;
            float2 lo = make_float2(acc[mt][nt][0] * qs + sbias[col],
                                    acc[mt][nt][1] * qs + sbias[col + 1]);
            float2 hi = make_float2(acc[mt][nt][2] * qs + sbias[col],
                                    acc[mt][nt][3] * qs + sbias[col + 1]);
            *reinterpret_cast<float2*>(stg + row * 136 + col)       = lo;
            *reinterpret_cast<float2*>(stg + (row + 8) * 136 + col) = hi;
        }
    __syncthreads();

    const float4* s4 = reinterpret_cast<const float4*>(stg);
    float4* o4 = reinterpret_cast<float4*>(out);
#pragma unroll
    for (int i = 0; i < 16; i++) {
        const int idx = tid + i * 256;
        const int r = idx >> 5, c4 = idx & 31;
        o4[(size_t)(mtile * 128 + r) * (N_TOTAL / 4) + ntile * 32 + c4] = s4[r * 34 + c4];
    }
}

// ---------------------------------------------------------------------------
extern "C" void kernel_launch(void* const* d_in, const int* in_sizes, int n_in,
                              void* d_out, int out_size) {
    const float* x     = (const float*)d_in[0];
    const int*   wq    = (const int*)d_in[1];
    const float* scale = (const float*)d_in[2];
    const float* bias  = (const float*)d_in[3];
    float* out = (float*)d_out;

    pack_kernel<<<49152, 256>>>(x, wq);

    cudaFuncSetAttribute(qgemm_kernel,
                         cudaFuncAttributeMaxDynamicSharedMemorySize, DYN_SMEM);
    dim3 grid(NUM_NT, NUM_MT);   // ntile fast: wave shares A rows, B L2-resident
    qgemm_kernel<<<grid, 256, DYN_SMEM>>>(scale, bias, out);
}

// round 7
// speedup vs baseline: 6.5594x; 1.0078x over previous
#include <cuda_runtime.h>
#include <cuda_fp16.h>
#include <cstdint>

// ============================================================================
// QuantizedLinear, sm_103 base-PTX build (no tcgen05 in this toolchain).
// R3: classic fp16 HMMA native, 1437us (tensor 66.5%, 1 CTA/SM).
// R4: 2 CTAs/SM -> 1269us (75.8%).
// R5: decoupled producer/consumer mbarrier ring -> 1126us (86.1%).
// R6: chunk-head stall removal:
//     (a) next-chunk full-wait hoisted between last loads and last MMA group
//         of the current chunk (wakeup latency overlapped by HMMA drain),
//     (b) B fragments paired into 16B slots -> LDS.128 (half the LDS instrs).
//   x -> fp16 (rel sigma ~1.7e-4), wq (0..126) -> fp16 exact,
//   y = (x_h @ w_h^T)*scale + bias, fp32 accum.  HMMA floor ~907us GEMM.
// ============================================================================

#define M_TOTAL 16384
#define N_TOTAL 4096
#define K_TOTAL 4096
#define NUM_KS  64            // K chunks of 64
#define NUM_MT  128           // M tiles of 128
#define NUM_NT  32            // N tiles of 128
#define STAGES  3

#define A_CHUNK_BYTES 16384   // 128m x 64k fp16, frag-ordered
#define B_CHUNK_BYTES 16384   // 128n x 64k fp16, frag-ordered (paired 16B slots)
#define STAGE_BYTES   (A_CHUNK_BYTES + B_CHUNK_BYTES)   // 32768

#define SMEM_BIAS   512
#define SMEM_STAGE0 1024
#define DYN_SMEM    (SMEM_STAGE0 + STAGES * STAGE_BYTES)  // 99328 -> 2 CTAs/SM

__device__ __align__(1024) unsigned char g_A[(size_t)NUM_MT * NUM_KS * A_CHUNK_BYTES]; // 128 MB
__device__ __align__(1024) unsigned char g_B[(size_t)NUM_NT * NUM_KS * B_CHUNK_BYTES]; //  32 MB

// ---------------------------------------------------------------------------
__device__ __forceinline__ uint32_t smem_u32(const void* p) {
    uint32_t a;
    asm("{ .reg .u64 t; cvta.to.shared.u64 t, %1; cvt.u32.u64 %0, t; }" : "=r"(a) : "l"(p));
    return a;
}

#define MBARRIER_INIT(addr, cnt) \
    asm volatile("mbarrier.init.shared.b64 [%0], %1;" :: "r"((uint32_t)(addr)), "r"((uint32_t)(cnt)) : "memory")
#define MBARRIER_EXPECT_TX(addr, bytes) \
    asm volatile("mbarrier.arrive.expect_tx.shared.b64 _, [%0], %1;" :: "r"((uint32_t)(addr)), "r"((uint32_t)(bytes)) : "memory")
#define MBARRIER_ARRIVE(addr) \
    asm volatile("mbarrier.arrive.shared.b64 _, [%0];" :: "r"((uint32_t)(addr)) : "memory")

#define MBARRIER_WAIT_PARITY(addr, parity) do {                                   \
    uint32_t _m = (uint32_t)(addr); uint32_t _p = (uint32_t)(parity); uint32_t _d;\
    asm volatile("{\n\t.reg .pred p;\n\t"                                         \
        "mbarrier.try_wait.parity.acquire.cta.shared::cta.b64 p, [%1], %2;\n\t"   \
        "selp.b32 %0, 1, 0, p;\n\t}"                                              \
        : "=r"(_d) : "r"(_m), "r"(_p) : "memory");                                \
    if (!_d) {                                                                    \
        asm volatile("{\n\t.reg .pred P1;\n\t"                                    \
            "WAIT_LOOP_%=:\n\t"                                                   \
            "mbarrier.try_wait.parity.acquire.cta.shared::cta.b64 P1, [%0], %1, 0x989680;\n\t" \
            "@P1 bra.uni WAIT_DONE_%=;\n\t"                                       \
            "bra.uni WAIT_LOOP_%=;\n\t"                                           \
            "WAIT_DONE_%=:\n\t}"                                                  \
            :: "r"(_m), "r"(_p) : "memory");                                      \
    }                                                                             \
} while (0)

// relaxed wait: OK for producer whose post-wait smem writes are async-proxy (bulk DMA)
#define MBARRIER_WAIT_PARITY_RELAXED(addr, parity) do {                           \
    uint32_t _m = (uint32_t)(addr); uint32_t _p = (uint32_t)(parity); uint32_t _d;\
    asm volatile("{\n\t.reg .pred p;\n\t"                                         \
        "mbarrier.try_wait.parity.relaxed.cta.shared::cta.b64 p, [%1], %2;\n\t"   \
        "selp.b32 %0, 1, 0, p;\n\t}"                                              \
        : "=r"(_d) : "r"(_m), "r"(_p) : "memory");                                \
    if (!_d) {                                                                    \
        asm volatile("{\n\t.reg .pred P1;\n\t"                                    \
            "WAIT_LOOP_%=:\n\t"                                                   \
            "mbarrier.try_wait.parity.relaxed.cta.shared::cta.b64 P1, [%0], %1, 0x989680;\n\t" \
            "@P1 bra.uni WAIT_DONE_%=;\n\t"                                       \
            "bra.uni WAIT_LOOP_%=;\n\t"                                           \
            "WAIT_DONE_%=:\n\t}"                                                  \
            :: "r"(_m), "r"(_p) : "memory");                                      \
    }                                                                             \
} while (0)

__device__ __forceinline__ void bulk_g2s(uint32_t dst, const void* src,
                                         uint32_t bytes, uint32_t mbar) {
    asm volatile(
        "cp.async.bulk.shared::cluster.global.mbarrier::complete_tx::bytes [%0], [%1], %2, [%3];"
        :: "r"(dst), "l"(src), "r"(bytes), "r"(mbar) : "memory");
}

// fp16 HMMA: D(f32, m16n8) += A(f16, m16k16) * B(f16, k16n8)
__device__ __forceinline__ void mma_f16(float* d, const uint32_t* a, const uint32_t* b) {
    asm volatile(
        "mma.sync.aligned.m16n8k16.row.col.f32.f16.f16.f32 "
        "{%0,%1,%2,%3}, {%4,%5,%6,%7}, {%8,%9}, {%0,%1,%2,%3};"
        : "+f"(d[0]), "+f"(d[1]), "+f"(d[2]), "+f"(d[3])
        : "r"(a[0]), "r"(a[1]), "r"(a[2]), "r"(a[3]), "r"(b[0]), "r"(b[1]));
}

__device__ __forceinline__ uint32_t h2(float a, float b) {
    __half2 h = __floats2half2_rn(a, b);
    return *reinterpret_cast<uint32_t*>(&h);
}

// ---------------------------------------------------------------------------
// Fused pack kernel.
//  A-part (blocks 0..32767): x fp32 -> fp16 frags, 16B slots.
//    slot = ((mw*4+kk)*2+mt)*32 + lane.
//  B-part (blocks 32768..40959): wq -> fp16, PAIRED frags: 16B slot holds
//    frag nt=2p (rows n..n+7) and nt=2p+1 (rows n+8..n+15) for one lane.
//    slot = ((nw*4+kk)*4+p)*32 + lane.
// ---------------------------------------------------------------------------
__global__ void __launch_bounds__(256) pack_kernel(const float* __restrict__ x,
                                                   const int* __restrict__ wq) {
    if (blockIdx.x < 32768) {
        const int t = blockIdx.x * 256 + threadIdx.x;
        const int chunk = t >> 10, slot = t & 1023;
        const int mtile = chunk >> 6, ks = chunk & 63;
        const int lane = slot & 31, mt = (slot >> 5) & 1, kk = (slot >> 6) & 3, mw = slot >> 8;
        const int m0 = mtile * 128 + mw * 32 + mt * 16 + (lane >> 2);
        const int kb = ks * 64 + kk * 16 + (lane & 3) * 2;
        const float* p0 = x + (size_t)m0 * K_TOTAL + kb;
        const float* p8 = p0 + 8 * K_TOTAL;
        const float2 f00 = *reinterpret_cast<const float2*>(p0);
        const float2 f10 = *reinterpret_cast<const float2*>(p8);
        const float2 f01 = *reinterpret_cast<const float2*>(p0 + 8);
        const float2 f11 = *reinterpret_cast<const float2*>(p8 + 8);
        uint4 v;
        v.x = h2(f00.x, f00.y);
        v.y = h2(f10.x, f10.y);
        v.z = h2(f01.x, f01.y);
        v.w = h2(f11.x, f11.y);
        *reinterpret_cast<uint4*>(g_A + ((size_t)chunk << 14) + ((size_t)slot << 4)) = v;
    } else {
        const int t = (blockIdx.x - 32768) * 256 + threadIdx.x;  // 2,097,152 threads
        const int chunk = t >> 10, slot = t & 1023;
        const int ntile = chunk >> 6, ks = chunk & 63;
        const int lane = slot & 31, p = (slot >> 5) & 3, kk = (slot >> 7) & 3, nw = slot >> 9;
        const int n0 = ntile * 128 + nw * 64 + p * 16 + (lane >> 2);  // frag nt=2p
        const int kb = ks * 64 + kk * 16 + (lane & 3) * 2;
        const int* qa = wq + (size_t)n0 * K_TOTAL + kb;
        const int* qb = qa + 8 * (size_t)K_TOTAL;                     // frag nt=2p+1
        const int2 a0 = *reinterpret_cast<const int2*>(qa);
        const int2 a1 = *reinterpret_cast<const int2*>(qa + 8);
        const int2 b0 = *reinterpret_cast<const int2*>(qb);
        const int2 b1 = *reinterpret_cast<const int2*>(qb + 8);
        uint4 v;
        v.x = h2((float)a0.x, (float)a0.y);
        v.y = h2((float)a1.x, (float)a1.y);
        v.z = h2((float)b0.x, (float)b0.y);
        v.w = h2((float)b1.x, (float)b1.y);
        *reinterpret_cast<uint4*>(g_B + ((size_t)chunk << 14) + ((size_t)slot << 4)) = v;
    }
}

// ---------------------------------------------------------------------------
// GEMM: CTA 128x128, 256 thr = 8 warps (4m x 2n), warp tile 32x64.
// Decoupled ring: full[s] (count 1, tx) / empty[s] (count 8).
// Next-chunk full-wait hoisted between kk=3 loads and kk=3 MMAs.
// ---------------------------------------------------------------------------
__global__ void __launch_bounds__(256, 2) qgemm_kernel(
    const float* __restrict__ scale_p,
    const float* __restrict__ bias,
    float* __restrict__ out)
{
    extern __shared__ __align__(128) unsigned char smem[];
    const uint32_t sb = smem_u32(smem);
    const int tid = threadIdx.x, lane = tid & 31, warp = tid >> 5;
    const int mw = warp & 3, nw = warp >> 2;
    const int ntile = blockIdx.x, mtile = blockIdx.y;

    // mbarriers: full[s] @ sb + s*16, empty[s] @ sb + s*16 + 8
    if (tid < STAGES) {
        MBARRIER_INIT(sb + tid * 16, 1);        // full: tx-completion
        MBARRIER_INIT(sb + tid * 16 + 8, 8);    // empty: 8 warp arrivals
    }
    float* sbias = reinterpret_cast<float*>(smem + SMEM_BIAS);
    if (tid < 128) sbias[tid] = bias[ntile * 128 + tid];
    const float qs = scale_p[0];
    __syncthreads();

    const unsigned char* gA = g_A + (((size_t)mtile * NUM_KS) << 14);
    const unsigned char* gB = g_B + (((size_t)ntile * NUM_KS) << 14);

    // prologue: fill chunks 0..STAGES-2
    if (tid == 0) {
#pragma unroll
        for (int s = 0; s < STAGES - 1; s++) {
            const uint32_t mbar = sb + s * 16;
            const uint32_t dst  = sb + SMEM_STAGE0 + s * STAGE_BYTES;
            MBARRIER_EXPECT_TX(mbar, STAGE_BYTES);
            bulk_g2s(dst, gA + ((size_t)s << 14), A_CHUNK_BYTES, mbar);
            bulk_g2s(dst + A_CHUNK_BYTES, gB + ((size_t)s << 14), B_CHUNK_BYTES, mbar);
        }
    }

    float acc[2][8][4];
#pragma unroll
    for (int mt = 0; mt < 2; mt++)
#pragma unroll
        for (int nt = 0; nt < 8; nt++)
#pragma unroll
            for (int j = 0; j < 4; j++) acc[mt][nt][j] = 0.0f;

    // wait for chunk 0 (head waits for later chunks are hoisted into loop tails)
    MBARRIER_WAIT_PARITY(sb + 0 * 16, 0);

    for (int ks = 0; ks < NUM_KS; ks++) {
        const int s = ks % STAGES;

        // producer duty (warp 0 lane 0): refill chunk ks+STAGES-1 into its stage
        if (tid == 0) {
            const int ks2 = ks + STAGES - 1;
            if (ks2 < NUM_KS) {
                const int s2 = ks2 % STAGES;
                if (ks2 >= STAGES) {
                    MBARRIER_WAIT_PARITY_RELAXED(sb + s2 * 16 + 8,
                                                 ((ks2 / STAGES) - 1) & 1);
                }
                const uint32_t mbar = sb + s2 * 16;
                const uint32_t dst  = sb + SMEM_STAGE0 + s2 * STAGE_BYTES;
                MBARRIER_EXPECT_TX(mbar, STAGE_BYTES);
                bulk_g2s(dst, gA + ((size_t)ks2 << 14), A_CHUNK_BYTES, mbar);
                bulk_g2s(dst + A_CHUNK_BYTES, gB + ((size_t)ks2 << 14),
                         B_CHUNK_BYTES, mbar);
            }
        }

        const unsigned char* st = smem + SMEM_STAGE0 + s * STAGE_BYTES;

#pragma unroll
        for (int kk = 0; kk < 4; kk++) {
            uint32_t afr[2][4];
            uint32_t bfr[8][2];
#pragma unroll
            for (int mt = 0; mt < 2; mt++) {
                const uint4 v = *reinterpret_cast<const uint4*>(
                    st + ((((mw * 4 + kk) * 2 + mt) * 32 + lane) << 4));
                afr[mt][0] = v.x; afr[mt][1] = v.y; afr[mt][2] = v.z; afr[mt][3] = v.w;
            }
#pragma unroll
            for (int p = 0; p < 4; p++) {
                const uint4 v = *reinterpret_cast<const uint4*>(
                    st + A_CHUNK_BYTES + ((((nw * 4 + kk) * 4 + p) * 32 + lane) << 4));
                bfr[2 * p][0]     = v.x; bfr[2 * p][1]     = v.y;
                bfr[2 * p + 1][0] = v.z; bfr[2 * p + 1][1] = v.w;
            }

            // hoisted wait: after the LAST loads of this chunk, before its
            // last MMA group — wakeup latency overlapped by HMMA drain.
            if (kk == 3 && ks + 1 < NUM_KS) {
                const int ns = (ks + 1) % STAGES;
                MBARRIER_WAIT_PARITY(sb + ns * 16, ((ks + 1) / STAGES) & 1);
            }

#pragma unroll
            for (int mt = 0; mt < 2; mt++)
#pragma unroll
                for (int nt = 0; nt < 8; nt++)
                    mma_f16(acc[mt][nt], afr[mt], bfr[nt]);
        }

        // this warp is done reading stage s
        if (lane == 0) MBARRIER_ARRIVE(sb + s * 16 + 8);
    }

    // ------------------------------ epilogue ------------------------------
    __syncthreads();   // stage buffers free (all warps past chunk 63)
    float* stg = reinterpret_cast<float*>(smem + SMEM_STAGE0);   // 128 x 136 f
    const int r0 = mw * 32 + (lane >> 2);
    const int cb = nw * 64 + (lane & 3) * 2;

#pragma unroll
    for (int mt = 0; mt < 2; mt++)
#pragma unroll
        for (int nt = 0; nt < 8; nt++) {
            const int row = r0 + mt * 16;
            const int col = cb + nt * 8;
            float2 lo = make_float2(acc[mt][nt][0] * qs + sbias[col],
                                    acc[mt][nt][1] * qs + sbias[col + 1]);
            float2 hi = make_float2(acc[mt][nt][2] * qs + sbias[col],
                                    acc[mt][nt][3] * qs + sbias[col + 1]);
            *reinterpret_cast<float2*>(stg + row * 136 + col)       = lo;
            *reinterpret_cast<float2*>(stg + (row + 8) * 136 + col) = hi;
        }
    __syncthreads();

    const float4* s4 = reinterpret_cast<const float4*>(stg);
    float4* o4 = reinterpret_cast<float4*>(out);
#pragma unroll
    for (int i = 0; i < 16; i++) {
        const int idx = tid + i * 256;
        const int r = idx >> 5, c4 = idx & 31;
        o4[(size_t)(mtile * 128 + r) * (N_TOTAL / 4) + ntile * 32 + c4] = s4[r * 34 + c4];
    }
}

// ---------------------------------------------------------------------------
extern "C" void kernel_launch(void* const* d_in, const int* in_sizes, int n_in,
                              void* d_out, int out_size) {
    const float* x     = (const float*)d_in[0];
    const int*   wq    = (const int*)d_in[1];
    const float* scale = (const float*)d_in[2];
    const float* bias  = (const float*)d_in[3];
    float* out = (float*)d_out;

    pack_kernel<<<40960, 256>>>(x, wq);   // 32768 A-blocks + 8192 B-blocks

    cudaFuncSetAttribute(qgemm_kernel,
                         cudaFuncAttributeMaxDynamicSharedMemorySize, DYN_SMEM);
    dim3 grid(NUM_NT, NUM_MT);   // ntile fast: wave shares A rows, B L2-resident
    qgemm_kernel<<<grid, 256, DYN_SMEM>>>(scale, bias, out);
}